// round 7
// baseline (speedup 1.0000x reference)
#include <cuda_runtime.h>

#define N_NODES 50000
#define N_EDGES 600000
#define DIM 128
#define LN_EPS 1e-5f

// ---- scratch (no allocations allowed) ----
__device__ float g_agg[(size_t)N_NODES * DIM];   // 25.6 MB
__device__ int   g_deg_src[N_NODES];
__device__ int   g_deg_dst[N_NODES];

// ---------------------------------------------------------------------------
// 1) zero agg + degree counters
// ---------------------------------------------------------------------------
__global__ void zero_kernel() {
    int idx = blockIdx.x * blockDim.x + threadIdx.x;
    const int n4 = N_NODES * DIM / 4;           // 1.6M float4
    if (idx < n4) ((float4*)g_agg)[idx] = make_float4(0.f, 0.f, 0.f, 0.f);
    if (idx < N_NODES) { g_deg_src[idx] = 0; g_deg_dst[idx] = 0; }
}

// ---------------------------------------------------------------------------
// 2) degree histogram
// ---------------------------------------------------------------------------
__global__ void deg_kernel(const int* __restrict__ src, const int* __restrict__ dst) {
    int e = blockIdx.x * blockDim.x + threadIdx.x;
    if (e < N_EDGES) {
        atomicAdd(&g_deg_src[src[e]], 1);
        atomicAdd(&g_deg_dst[dst[e]], 1);
    }
}

// ---------------------------------------------------------------------------
// 3) edge scatter: agg[dst] += feat[src] * rsqrt(max(out_deg[src],1))
// ---------------------------------------------------------------------------
__global__ void scatter_kernel(const float* __restrict__ feat,
                               const int* __restrict__ src,
                               const int* __restrict__ dst) {
    int gid  = blockIdx.x * blockDim.x + threadIdx.x;
    int e    = gid >> 5;
    int lane = gid & 31;
    if (e >= N_EDGES) return;

    const int s = __ldg(&src[e]);
    const int d = __ldg(&dst[e]);
    const float scale = rsqrtf(fmaxf((float)g_deg_src[s], 1.0f));

    float4 v = __ldg((const float4*)(feat + (size_t)s * DIM) + lane);
    v.x *= scale; v.y *= scale; v.z *= scale; v.w *= scale;

    unsigned long long p = (unsigned long long)(g_agg + (size_t)d * DIM + lane * 4);
    asm volatile("red.global.add.v4.f32 [%0], {%1,%2,%3,%4};"
                 :: "l"(p), "f"(v.x), "f"(v.y), "f"(v.z), "f"(v.w)
                 : "memory");
}

// ---------------------------------------------------------------------------
// 4) fused GEMM + bias + residual + LayerNorm + ReLU
//    rst = [agg*in_norm | feat] @ [fc_w; res_w] + in_norm*fc_b
//    out = relu(layernorm(rst))
//    Tile: BM=128 x BN=128, BK=16. 256 threads as 16x16, each 8 rows x 8 cols.
//    A tile stored k-major (transposed) so a-frags are vectorized broadcasts.
//    LN done in-register via 16-lane shfl reductions (threads sharing ty own a row).
// ---------------------------------------------------------------------------
#define BM 128
#define BN 128
#define BK 16
#define SA_STR 132   // floats; 132*4B=528B rows stay 16B-aligned, <=2-way store conflicts

__global__ __launch_bounds__(256, 2) void gemm_ln_kernel(
    const float* __restrict__ feat,
    const float* __restrict__ fc_w,
    const float* __restrict__ fc_b,
    const float* __restrict__ res_w,
    const float* __restrict__ ln_g,
    const float* __restrict__ ln_b,
    float* __restrict__ out)
{
    __shared__ float sA[BK][SA_STR];    // k-major A tile (~8.4 KB)
    __shared__ float sW[BK][BN];        // W tile (8 KB)
    __shared__ float sInorm[BM];

    const int tid = threadIdx.x;
    const int tx  = tid & 15;           // col group: cols tx*4..+3 and 64+tx*4..+3
    const int ty  = tid >> 4;           // row group: rows ty*4..+3 and 64+ty*4..+3
    const int bm  = blockIdx.x * BM;

    if (tid < BM) {
        int node = bm + tid;
        float dn = (node < N_NODES) ? (float)g_deg_dst[node] : 1.0f;
        sInorm[tid] = rsqrtf(fmaxf(dn, 1.0f));
    }

    float acc[8][8];
#pragma unroll
    for (int i = 0; i < 8; i++)
#pragma unroll
        for (int j = 0; j < 8; j++) acc[i][j] = 0.f;

    for (int kt = 0; kt < 2 * DIM; kt += BK) {
        __syncthreads();   // sInorm ready (iter 0) + WAR on smem tiles

        // ---- stage W tile [BK][BN]: rows of [fc_w ; res_w] ----
#pragma unroll
        for (int i = 0; i < 2; i++) {
            int u  = tid + i * 256;      // 512 float4 units
            int k  = u >> 5;             // 0..15
            int c4 = u & 31;
            int kg = kt + k;
            const float* wrow = (kg < DIM) ? (fc_w + (size_t)kg * DIM)
                                           : (res_w + (size_t)(kg - DIM) * DIM);
            float4 w4 = __ldg((const float4*)wrow + c4);
            *((float4*)(&sW[k][0]) + c4) = w4;
        }

        // ---- stage A tile transposed: sA[k][m] = A2[bm+m][kt+k] ----
#pragma unroll
        for (int i = 0; i < 2; i++) {
            int u  = tid + i * 256;      // 512 float4 units
            int m  = u >> 2;             // 0..127
            int kq = u & 3;              // k-quad
            int node  = bm + m;
            int nodec = (node < N_NODES) ? node : (N_NODES - 1);
            int kg = kt + kq * 4;
            float4 a4;
            if (kg < DIM) {
                a4 = __ldg((const float4*)(g_agg + (size_t)nodec * DIM + kg));
                float sc = sInorm[m];
                a4.x *= sc; a4.y *= sc; a4.z *= sc; a4.w *= sc;
            } else {
                a4 = __ldg((const float4*)(feat + (size_t)nodec * DIM + (kg - DIM)));
            }
            sA[kq * 4 + 0][m] = a4.x;
            sA[kq * 4 + 1][m] = a4.y;
            sA[kq * 4 + 2][m] = a4.z;
            sA[kq * 4 + 3][m] = a4.w;
        }

        __syncthreads();

        // ---- compute: 64 FFMA per k per thread, 4 LDS.128 (2 broadcast) ----
#pragma unroll
        for (int k = 0; k < BK; k++) {
            float4 a0 = *(const float4*)&sA[k][ty * 4];
            float4 a1 = *(const float4*)&sA[k][64 + ty * 4];
            float4 b0 = *(const float4*)&sW[k][tx * 4];
            float4 b1 = *(const float4*)&sW[k][64 + tx * 4];
            float av[8] = {a0.x, a0.y, a0.z, a0.w, a1.x, a1.y, a1.z, a1.w};
            float bv[8] = {b0.x, b0.y, b0.z, b0.w, b1.x, b1.y, b1.z, b1.w};
#pragma unroll
            for (int i = 0; i < 8; i++)
#pragma unroll
                for (int j = 0; j < 8; j++)
                    acc[i][j] = fmaf(av[i], bv[j], acc[i][j]);
        }
    }

    // ---- epilogue: bias*in_norm, LayerNorm via 16-lane shuffles, ReLU ----
    float4 bias0 = __ldg((const float4*)fc_b + tx);
    float4 bias1 = __ldg((const float4*)fc_b + 16 + tx);
    float4 g0    = __ldg((const float4*)ln_g + tx);
    float4 g1    = __ldg((const float4*)ln_g + 16 + tx);
    float4 lb0   = __ldg((const float4*)ln_b + tx);
    float4 lb1   = __ldg((const float4*)ln_b + 16 + tx);
    float bias[8] = {bias0.x, bias0.y, bias0.z, bias0.w, bias1.x, bias1.y, bias1.z, bias1.w};
    float gam[8]  = {g0.x, g0.y, g0.z, g0.w, g1.x, g1.y, g1.z, g1.w};
    float bet[8]  = {lb0.x, lb0.y, lb0.z, lb0.w, lb1.x, lb1.y, lb1.z, lb1.w};

#pragma unroll
    for (int i = 0; i < 8; i++) {
        int row  = (i < 4) ? (ty * 4 + i) : (64 + ty * 4 + (i - 4));
        float inn = sInorm[row];
        float v[8];
        float s = 0.f, q = 0.f;
#pragma unroll
        for (int j = 0; j < 8; j++) {
            v[j] = acc[i][j] + inn * bias[j];
            s += v[j];
            q += v[j] * v[j];
        }
        // reduce across the 16 lanes sharing this row (tx = lane & 15)
#pragma unroll
        for (int off = 8; off > 0; off >>= 1) {
            s += __shfl_xor_sync(0xffffffffu, s, off);
            q += __shfl_xor_sync(0xffffffffu, q, off);
        }
        float mu   = s * (1.0f / DIM);
        float var  = q * (1.0f / DIM) - mu * mu;
        float rstd = rsqrtf(var + LN_EPS);

        int node = bm + row;
        if (node < N_NODES) {
            float o[8];
#pragma unroll
            for (int j = 0; j < 8; j++)
                o[j] = fmaxf(0.f, (v[j] - mu) * rstd * gam[j] + bet[j]);
            float* orow = out + (size_t)node * DIM;
            *((float4*)orow + tx)      = make_float4(o[0], o[1], o[2], o[3]);
            *((float4*)orow + 16 + tx) = make_float4(o[4], o[5], o[6], o[7]);
        }
    }
}

// ---------------------------------------------------------------------------
extern "C" void kernel_launch(void* const* d_in, const int* in_sizes, int n_in,
                              void* d_out, int out_size) {
    const float* feat  = (const float*)d_in[0];
    const int*   src   = (const int*)d_in[1];
    const int*   dst   = (const int*)d_in[2];
    const float* fc_w  = (const float*)d_in[3];
    const float* fc_b  = (const float*)d_in[4];
    const float* res_w = (const float*)d_in[5];
    const float* ln_g  = (const float*)d_in[6];
    const float* ln_b  = (const float*)d_in[7];
    float* out = (float*)d_out;

    (void)in_sizes; (void)n_in; (void)out_size;

    zero_kernel<<<(N_NODES * DIM / 4 + 255) / 256, 256>>>();
    deg_kernel<<<(N_EDGES + 255) / 256, 256>>>(src, dst);
    scatter_kernel<<<(N_EDGES * 32) / 256, 256>>>(feat, src, dst);
    gemm_ln_kernel<<<(N_NODES + BM - 1) / BM, 256>>>(feat, fc_w, fc_b, res_w,
                                                     ln_g, ln_b, out);
}

// round 13
// speedup vs baseline: 1.5118x; 1.5118x over previous
#include <cuda_runtime.h>
#include <cstdint>

#define N_NODES 50000
#define N_EDGES 600000
#define DIM 128
#define LN_EPS 1e-5f

// ---- scratch (no allocations allowed) ----
__device__ float g_agg[(size_t)N_NODES * DIM];   // 25.6 MB
__device__ int   g_deg_src[N_NODES];
__device__ int   g_deg_dst[N_NODES];

// ---------------------------------------------------------------------------
// 1) zero agg + degree counters
// ---------------------------------------------------------------------------
__global__ void zero_kernel() {
    int idx = blockIdx.x * blockDim.x + threadIdx.x;
    const int n4 = N_NODES * DIM / 4;
    if (idx < n4) ((float4*)g_agg)[idx] = make_float4(0.f, 0.f, 0.f, 0.f);
    if (idx < N_NODES) { g_deg_src[idx] = 0; g_deg_dst[idx] = 0; }
}

// ---------------------------------------------------------------------------
// 2) degree histogram
// ---------------------------------------------------------------------------
__global__ void deg_kernel(const int* __restrict__ src, const int* __restrict__ dst) {
    int e = blockIdx.x * blockDim.x + threadIdx.x;
    if (e < N_EDGES) {
        atomicAdd(&g_deg_src[src[e]], 1);
        atomicAdd(&g_deg_dst[dst[e]], 1);
    }
}

// ---------------------------------------------------------------------------
// 3) edge scatter: agg[dst] += feat[src] * rsqrt(max(out_deg[src],1))
// ---------------------------------------------------------------------------
__global__ void scatter_kernel(const float* __restrict__ feat,
                               const int* __restrict__ src,
                               const int* __restrict__ dst) {
    int gid  = blockIdx.x * blockDim.x + threadIdx.x;
    int e    = gid >> 5;
    int lane = gid & 31;
    if (e >= N_EDGES) return;

    const int s = __ldg(&src[e]);
    const int d = __ldg(&dst[e]);
    const float scale = rsqrtf(fmaxf((float)g_deg_src[s], 1.0f));

    float4 v = __ldg((const float4*)(feat + (size_t)s * DIM) + lane);
    v.x *= scale; v.y *= scale; v.z *= scale; v.w *= scale;

    unsigned long long p = (unsigned long long)(g_agg + (size_t)d * DIM + lane * 4);
    asm volatile("red.global.add.v4.f32 [%0], {%1,%2,%3,%4};"
                 :: "l"(p), "f"(v.x), "f"(v.y), "f"(v.z), "f"(v.w)
                 : "memory");
}

// ---------------------------------------------------------------------------
// 4) mma.sync TF32 GEMM + bias + residual + LayerNorm + ReLU
//    rst = [agg*in_norm | feat] @ [fc_w; res_w] + in_norm*fc_b
//    Block 128x128xK256 (BK=32). 8 warps = 4(M) x 2(N); warp = 32x64
//    = 2 m-tiles x 8 n-tiles of m16n8k8 tf32.
// ---------------------------------------------------------------------------
#define SA_S 36    // sA row stride (floats): frag-load bank = 4*gid+tig (distinct)
#define SB_S 136   // sB row stride (floats): frag-load bank = 8*tig+gid (distinct)

static __device__ __forceinline__ uint32_t f2tf32(float f) {
    uint32_t u;
    asm("cvt.rna.tf32.f32 %0, %1;" : "=r"(u) : "f"(f));
    return u;
}

static __device__ __forceinline__ void mma_tf32(
    float c[4], const uint32_t a[4], uint32_t b0, uint32_t b1) {
    asm volatile(
        "mma.sync.aligned.m16n8k8.row.col.f32.tf32.tf32.f32 "
        "{%0,%1,%2,%3}, {%4,%5,%6,%7}, {%8,%9}, {%0,%1,%2,%3};"
        : "+f"(c[0]), "+f"(c[1]), "+f"(c[2]), "+f"(c[3])
        : "r"(a[0]), "r"(a[1]), "r"(a[2]), "r"(a[3]), "r"(b0), "r"(b1));
}

__global__ __launch_bounds__(256, 2) void gemm_mma_kernel(
    const float* __restrict__ feat,
    const float* __restrict__ fc_w,
    const float* __restrict__ fc_b,
    const float* __restrict__ res_w,
    const float* __restrict__ ln_g,
    const float* __restrict__ ln_b,
    float* __restrict__ out)
{
    __shared__ __align__(16) uint32_t sA[128 * SA_S];   // 18.4 KB (tf32 bits)
    __shared__ __align__(16) uint32_t sB[32 * SB_S];    // 17.4 KB (tf32 bits)
    __shared__ float sInorm[128], sBias[128], sGam[128], sBet[128];
    __shared__ float sSum[2][128], sSq[2][128];

    const int tid   = threadIdx.x;
    const int lane  = tid & 31;
    const int wid   = tid >> 5;
    const int warpM = wid & 3;          // 0..3 -> rows warpM*32..+31
    const int warpN = wid >> 2;         // 0..1 -> cols warpN*64..+63
    const int gid   = lane >> 2;        // 0..7
    const int tig   = lane & 3;         // 0..3
    const int bm    = blockIdx.x * 128;

    if (tid < 128) {
        int node = bm + tid;
        float dn = (node < N_NODES) ? (float)g_deg_dst[node] : 1.0f;
        sInorm[tid] = rsqrtf(fmaxf(dn, 1.0f));
        sBias[tid]  = __ldg(&fc_b[tid]);
        sGam[tid]   = __ldg(&ln_g[tid]);
        sBet[tid]   = __ldg(&ln_b[tid]);
    }

    float acc[2][8][4];
#pragma unroll
    for (int mt = 0; mt < 2; mt++)
#pragma unroll
        for (int nt = 0; nt < 8; nt++)
#pragma unroll
            for (int e = 0; e < 4; e++) acc[mt][nt][e] = 0.f;

    for (int kt = 0; kt < 2 * DIM; kt += 32) {
        __syncthreads();   // sInorm ready (iter 0) + WAR on tiles

        // ---- stage A chunk [128 m][32 k] as tf32 (float4 -> uint4 stores) ----
#pragma unroll
        for (int i = 0; i < 4; i++) {
            int u = tid + i * 256;          // 1024 float4 units
            int m = u >> 3;                 // 0..127
            int q = u & 7;                  // k-quad 0..7
            int node  = bm + m;
            int nodec = (node < N_NODES) ? node : (N_NODES - 1);
            int kg = kt + q * 4;
            float4 a4;
            if (kg < DIM) {
                a4 = __ldg((const float4*)(g_agg + (size_t)nodec * DIM + kg));
                float sc = sInorm[m];
                a4.x *= sc; a4.y *= sc; a4.z *= sc; a4.w *= sc;
            } else {
                a4 = __ldg((const float4*)(feat + (size_t)nodec * DIM + (kg - DIM)));
            }
            uint4 t;
            t.x = f2tf32(a4.x); t.y = f2tf32(a4.y);
            t.z = f2tf32(a4.z); t.w = f2tf32(a4.w);
            *(uint4*)(sA + m * SA_S + q * 4) = t;
        }

        // ---- stage B chunk: sB[kk][n] = W[kt+kk][n] (k-major, coalesced) ----
#pragma unroll
        for (int i = 0; i < 4; i++) {
            int u  = tid + i * 256;         // 1024 float4 units
            int kk = u >> 5;                // 0..31
            int n4 = u & 31;                // float4 along n
            int kg = kt + kk;
            const float* wrow = (kg < DIM) ? (fc_w + (size_t)kg * DIM)
                                           : (res_w + (size_t)(kg - DIM) * DIM);
            float4 w4 = __ldg((const float4*)wrow + n4);
            uint4 t;
            t.x = f2tf32(w4.x); t.y = f2tf32(w4.y);
            t.z = f2tf32(w4.z); t.w = f2tf32(w4.w);
            *(uint4*)(sB + kk * SB_S + n4 * 4) = t;
        }
        __syncthreads();

        // ---- compute: 4 k8-steps x (2 m-tiles x 8 n-tiles) mma ----
#pragma unroll
        for (int k8 = 0; k8 < 32; k8 += 8) {
            uint32_t af[2][4];
#pragma unroll
            for (int mt = 0; mt < 2; mt++) {
                int row0 = warpM * 32 + mt * 16 + gid;
                af[mt][0] = sA[row0 * SA_S + k8 + tig];
                af[mt][1] = sA[(row0 + 8) * SA_S + k8 + tig];
                af[mt][2] = sA[row0 * SA_S + k8 + tig + 4];
                af[mt][3] = sA[(row0 + 8) * SA_S + k8 + tig + 4];
            }
#pragma unroll
            for (int nt = 0; nt < 8; nt++) {
                int n = warpN * 64 + nt * 8 + gid;
                uint32_t b0 = sB[(k8 + tig) * SB_S + n];
                uint32_t b1 = sB[(k8 + tig + 4) * SB_S + n];
                mma_tf32(acc[0][nt], af[0], b0, b1);
                mma_tf32(acc[1][nt], af[1], b0, b1);
            }
        }
    }

    // ---- epilogue: bias*in_norm, partial LN sums (quad shuffle + smem) ----
#pragma unroll
    for (int mt = 0; mt < 2; mt++) {
#pragma unroll
        for (int h = 0; h < 2; h++) {
            int row = warpM * 32 + mt * 16 + h * 8 + gid;
            float inn = sInorm[row];
            float s = 0.f, q = 0.f;
#pragma unroll
            for (int nt = 0; nt < 8; nt++) {
#pragma unroll
                for (int e = 0; e < 2; e++) {
                    int col = warpN * 64 + nt * 8 + tig * 2 + e;
                    float val = acc[mt][nt][2 * h + e] + inn * sBias[col];
                    acc[mt][nt][2 * h + e] = val;
                    s += val; q += val * val;
                }
            }
            s += __shfl_xor_sync(0xffffffffu, s, 1);
            s += __shfl_xor_sync(0xffffffffu, s, 2);
            q += __shfl_xor_sync(0xffffffffu, q, 1);
            q += __shfl_xor_sync(0xffffffffu, q, 2);
            if (tig == 0) { sSum[warpN][row] = s; sSq[warpN][row] = q; }
        }
    }
    __syncthreads();

    // ---- LN + ReLU + store (float2 per n-tile, cols tig*2, tig*2+1) ----
#pragma unroll
    for (int mt = 0; mt < 2; mt++) {
#pragma unroll
        for (int h = 0; h < 2; h++) {
            int row = warpM * 32 + mt * 16 + h * 8 + gid;
            int node = bm + row;
            if (node >= N_NODES) continue;
            float s = sSum[0][row] + sSum[1][row];
            float q = sSq[0][row]  + sSq[1][row];
            float mu   = s * (1.0f / DIM);
            float var  = q * (1.0f / DIM) - mu * mu;
            float rstd = rsqrtf(var + LN_EPS);
            float* orow = out + (size_t)node * DIM;
#pragma unroll
            for (int nt = 0; nt < 8; nt++) {
                int col = warpN * 64 + nt * 8 + tig * 2;
                float2 o;
                o.x = fmaxf(0.f, (acc[mt][nt][2*h+0] - mu) * rstd * sGam[col]   + sBet[col]);
                o.y = fmaxf(0.f, (acc[mt][nt][2*h+1] - mu) * rstd * sGam[col+1] + sBet[col+1]);
                *(float2*)(orow + col) = o;
            }
        }
    }
}

// ---------------------------------------------------------------------------
extern "C" void kernel_launch(void* const* d_in, const int* in_sizes, int n_in,
                              void* d_out, int out_size) {
    const float* feat  = (const float*)d_in[0];
    const int*   src   = (const int*)d_in[1];
    const int*   dst   = (const int*)d_in[2];
    const float* fc_w  = (const float*)d_in[3];
    const float* fc_b  = (const float*)d_in[4];
    const float* res_w = (const float*)d_in[5];
    const float* ln_g  = (const float*)d_in[6];
    const float* ln_b  = (const float*)d_in[7];
    float* out = (float*)d_out;

    (void)in_sizes; (void)n_in; (void)out_size;

    zero_kernel<<<(N_NODES * DIM / 4 + 255) / 256, 256>>>();
    deg_kernel<<<(N_EDGES + 255) / 256, 256>>>(src, dst);
    scatter_kernel<<<(N_EDGES * 32) / 256, 256>>>(feat, src, dst);
    gemm_mma_kernel<<<(N_NODES + 127) / 128, 256>>>(feat, fc_w, fc_b, res_w,
                                                    ln_g, ln_b, out);
}

// round 14
// speedup vs baseline: 1.9484x; 1.2888x over previous
#include <cuda_runtime.h>
#include <cstdint>

#define N_NODES 50000
#define N_EDGES 600000
#define DIM 128
#define LN_EPS 1e-5f
#define CAP 96            // bucket capacity; dst ~ Poisson(12), P(>=96) ~ 1e-40

// ---- scratch (no allocations allowed) ----
__device__ float g_agg[(size_t)N_NODES * DIM];    // 25.6 MB
__device__ int   g_deg_src[N_NODES];
__device__ int   g_deg_dst[N_NODES];
__device__ int   g_fill[N_NODES];
__device__ int   g_bucket[(size_t)N_NODES * CAP]; // 19.2 MB
__device__ float g_onorm[N_NODES];

// ---------------------------------------------------------------------------
// 1) zero counters (agg no longer needs zeroing: gather writes it fully)
// ---------------------------------------------------------------------------
__global__ void zero_kernel() {
    int idx = blockIdx.x * blockDim.x + threadIdx.x;
    if (idx < N_NODES) { g_deg_src[idx] = 0; g_deg_dst[idx] = 0; g_fill[idx] = 0; }
}

// ---------------------------------------------------------------------------
// 2) degree histogram
// ---------------------------------------------------------------------------
__global__ void deg_kernel(const int* __restrict__ src, const int* __restrict__ dst) {
    int e = blockIdx.x * blockDim.x + threadIdx.x;
    if (e < N_EDGES) {
        atomicAdd(&g_deg_src[src[e]], 1);
        atomicAdd(&g_deg_dst[dst[e]], 1);
    }
}

// ---------------------------------------------------------------------------
// 3) per-src out-norm
// ---------------------------------------------------------------------------
__global__ void onorm_kernel() {
    int i = blockIdx.x * blockDim.x + threadIdx.x;
    if (i < N_NODES) g_onorm[i] = rsqrtf(fmaxf((float)g_deg_src[i], 1.0f));
}

// ---------------------------------------------------------------------------
// 4) bin edges by dst: bucket[d][pos] = src
// ---------------------------------------------------------------------------
__global__ void fill_kernel(const int* __restrict__ src, const int* __restrict__ dst) {
    int e = blockIdx.x * blockDim.x + threadIdx.x;
    if (e >= N_EDGES) return;
    int d = __ldg(&dst[e]);
    int pos = atomicAdd(&g_fill[d], 1);
    if (pos < CAP) g_bucket[(size_t)d * CAP + pos] = __ldg(&src[e]);
}

// ---------------------------------------------------------------------------
// 5) pull-mode gather: one warp per dst node
//    agg[d] = sum_{s in bucket[d]} feat[s] * onorm[s]
// ---------------------------------------------------------------------------
__global__ void gather_kernel(const float* __restrict__ feat) {
    int gid  = blockIdx.x * blockDim.x + threadIdx.x;
    int d    = gid >> 5;
    int lane = gid & 31;
    if (d >= N_NODES) return;

    int cnt = min(__ldg(&g_fill[d]), CAP);
    float4 acc = make_float4(0.f, 0.f, 0.f, 0.f);

    for (int base = 0; base < cnt; base += 32) {
        int nb = min(32, cnt - base);
        int   s  = 0;
        float sc = 0.f;
        if (lane < nb) {
            s  = g_bucket[(size_t)d * CAP + base + lane];
            sc = __ldg(&g_onorm[s]);
        }
#pragma unroll 4
        for (int i = 0; i < nb; i++) {
            int   si  = __shfl_sync(0xffffffffu, s,  i);
            float sci = __shfl_sync(0xffffffffu, sc, i);
            float4 v = __ldg((const float4*)(feat + (size_t)si * DIM) + lane);
            acc.x += sci * v.x; acc.y += sci * v.y;
            acc.z += sci * v.z; acc.w += sci * v.w;
        }
    }
    ((float4*)(g_agg + (size_t)d * DIM))[lane] = acc;
}

// ---------------------------------------------------------------------------
// 6) mma.sync TF32 GEMM + bias + residual + LayerNorm + ReLU  (unchanged)
// ---------------------------------------------------------------------------
#define SA_S 36
#define SB_S 136

static __device__ __forceinline__ uint32_t f2tf32(float f) {
    uint32_t u;
    asm("cvt.rna.tf32.f32 %0, %1;" : "=r"(u) : "f"(f));
    return u;
}

static __device__ __forceinline__ void mma_tf32(
    float c[4], const uint32_t a[4], uint32_t b0, uint32_t b1) {
    asm volatile(
        "mma.sync.aligned.m16n8k8.row.col.f32.tf32.tf32.f32 "
        "{%0,%1,%2,%3}, {%4,%5,%6,%7}, {%8,%9}, {%0,%1,%2,%3};"
        : "+f"(c[0]), "+f"(c[1]), "+f"(c[2]), "+f"(c[3])
        : "r"(a[0]), "r"(a[1]), "r"(a[2]), "r"(a[3]), "r"(b0), "r"(b1));
}

__global__ __launch_bounds__(256, 2) void gemm_mma_kernel(
    const float* __restrict__ feat,
    const float* __restrict__ fc_w,
    const float* __restrict__ fc_b,
    const float* __restrict__ res_w,
    const float* __restrict__ ln_g,
    const float* __restrict__ ln_b,
    float* __restrict__ out)
{
    __shared__ __align__(16) uint32_t sA[128 * SA_S];
    __shared__ __align__(16) uint32_t sB[32 * SB_S];
    __shared__ float sInorm[128], sBias[128], sGam[128], sBet[128];
    __shared__ float sSum[2][128], sSq[2][128];

    const int tid   = threadIdx.x;
    const int lane  = tid & 31;
    const int wid   = tid >> 5;
    const int warpM = wid & 3;
    const int warpN = wid >> 2;
    const int gid   = lane >> 2;
    const int tig   = lane & 3;
    const int bm    = blockIdx.x * 128;

    if (tid < 128) {
        int node = bm + tid;
        float dn = (node < N_NODES) ? (float)g_deg_dst[node] : 1.0f;
        sInorm[tid] = rsqrtf(fmaxf(dn, 1.0f));
        sBias[tid]  = __ldg(&fc_b[tid]);
        sGam[tid]   = __ldg(&ln_g[tid]);
        sBet[tid]   = __ldg(&ln_b[tid]);
    }

    float acc[2][8][4];
#pragma unroll
    for (int mt = 0; mt < 2; mt++)
#pragma unroll
        for (int nt = 0; nt < 8; nt++)
#pragma unroll
            for (int e = 0; e < 4; e++) acc[mt][nt][e] = 0.f;

    for (int kt = 0; kt < 2 * DIM; kt += 32) {
        __syncthreads();

#pragma unroll
        for (int i = 0; i < 4; i++) {
            int u = tid + i * 256;
            int m = u >> 3;
            int q = u & 7;
            int node  = bm + m;
            int nodec = (node < N_NODES) ? node : (N_NODES - 1);
            int kg = kt + q * 4;
            float4 a4;
            if (kg < DIM) {
                a4 = __ldg((const float4*)(g_agg + (size_t)nodec * DIM + kg));
                float sc = sInorm[m];
                a4.x *= sc; a4.y *= sc; a4.z *= sc; a4.w *= sc;
            } else {
                a4 = __ldg((const float4*)(feat + (size_t)nodec * DIM + (kg - DIM)));
            }
            uint4 t;
            t.x = f2tf32(a4.x); t.y = f2tf32(a4.y);
            t.z = f2tf32(a4.z); t.w = f2tf32(a4.w);
            *(uint4*)(sA + m * SA_S + q * 4) = t;
        }

#pragma unroll
        for (int i = 0; i < 4; i++) {
            int u  = tid + i * 256;
            int kk = u >> 5;
            int n4 = u & 31;
            int kg = kt + kk;
            const float* wrow = (kg < DIM) ? (fc_w + (size_t)kg * DIM)
                                           : (res_w + (size_t)(kg - DIM) * DIM);
            float4 w4 = __ldg((const float4*)wrow + n4);
            uint4 t;
            t.x = f2tf32(w4.x); t.y = f2tf32(w4.y);
            t.z = f2tf32(w4.z); t.w = f2tf32(w4.w);
            *(uint4*)(sB + kk * SB_S + n4 * 4) = t;
        }
        __syncthreads();

#pragma unroll
        for (int k8 = 0; k8 < 32; k8 += 8) {
            uint32_t af[2][4];
#pragma unroll
            for (int mt = 0; mt < 2; mt++) {
                int row0 = warpM * 32 + mt * 16 + gid;
                af[mt][0] = sA[row0 * SA_S + k8 + tig];
                af[mt][1] = sA[(row0 + 8) * SA_S + k8 + tig];
                af[mt][2] = sA[row0 * SA_S + k8 + tig + 4];
                af[mt][3] = sA[(row0 + 8) * SA_S + k8 + tig + 4];
            }
#pragma unroll
            for (int nt = 0; nt < 8; nt++) {
                int n = warpN * 64 + nt * 8 + gid;
                uint32_t b0 = sB[(k8 + tig) * SB_S + n];
                uint32_t b1 = sB[(k8 + tig + 4) * SB_S + n];
                mma_tf32(acc[0][nt], af[0], b0, b1);
                mma_tf32(acc[1][nt], af[1], b0, b1);
            }
        }
    }

#pragma unroll
    for (int mt = 0; mt < 2; mt++) {
#pragma unroll
        for (int h = 0; h < 2; h++) {
            int row = warpM * 32 + mt * 16 + h * 8 + gid;
            float inn = sInorm[row];
            float s = 0.f, q = 0.f;
#pragma unroll
            for (int nt = 0; nt < 8; nt++) {
#pragma unroll
                for (int e = 0; e < 2; e++) {
                    int col = warpN * 64 + nt * 8 + tig * 2 + e;
                    float val = acc[mt][nt][2 * h + e] + inn * sBias[col];
                    acc[mt][nt][2 * h + e] = val;
                    s += val; q += val * val;
                }
            }
            s += __shfl_xor_sync(0xffffffffu, s, 1);
            s += __shfl_xor_sync(0xffffffffu, s, 2);
            q += __shfl_xor_sync(0xffffffffu, q, 1);
            q += __shfl_xor_sync(0xffffffffu, q, 2);
            if (tig == 0) { sSum[warpN][row] = s; sSq[warpN][row] = q; }
        }
    }
    __syncthreads();

#pragma unroll
    for (int mt = 0; mt < 2; mt++) {
#pragma unroll
        for (int h = 0; h < 2; h++) {
            int row = warpM * 32 + mt * 16 + h * 8 + gid;
            int node = bm + row;
            if (node >= N_NODES) continue;
            float s = sSum[0][row] + sSum[1][row];
            float q = sSq[0][row]  + sSq[1][row];
            float mu   = s * (1.0f / DIM);
            float var  = q * (1.0f / DIM) - mu * mu;
            float rstd = rsqrtf(var + LN_EPS);
            float* orow = out + (size_t)node * DIM;
#pragma unroll
            for (int nt = 0; nt < 8; nt++) {
                int col = warpN * 64 + nt * 8 + tig * 2;
                float2 o;
                o.x = fmaxf(0.f, (acc[mt][nt][2*h+0] - mu) * rstd * sGam[col]   + sBet[col]);
                o.y = fmaxf(0.f, (acc[mt][nt][2*h+1] - mu) * rstd * sGam[col+1] + sBet[col+1]);
                *(float2*)(orow + col) = o;
            }
        }
    }
}

// ---------------------------------------------------------------------------
extern "C" void kernel_launch(void* const* d_in, const int* in_sizes, int n_in,
                              void* d_out, int out_size) {
    const float* feat  = (const float*)d_in[0];
    const int*   src   = (const int*)d_in[1];
    const int*   dst   = (const int*)d_in[2];
    const float* fc_w  = (const float*)d_in[3];
    const float* fc_b  = (const float*)d_in[4];
    const float* res_w = (const float*)d_in[5];
    const float* ln_g  = (const float*)d_in[6];
    const float* ln_b  = (const float*)d_in[7];
    float* out = (float*)d_out;

    (void)in_sizes; (void)n_in; (void)out_size;

    zero_kernel<<<(N_NODES + 255) / 256, 256>>>();
    deg_kernel<<<(N_EDGES + 255) / 256, 256>>>(src, dst);
    onorm_kernel<<<(N_NODES + 255) / 256, 256>>>();
    fill_kernel<<<(N_EDGES + 255) / 256, 256>>>(src, dst);
    gather_kernel<<<(N_NODES * 32 + 255) / 256, 256>>>(feat);
    gemm_mma_kernel<<<(N_NODES + 127) / 128, 256>>>(feat, fc_w, fc_b, res_w,
                                                    ln_g, ln_b, out);
}

// round 15
// speedup vs baseline: 2.1429x; 1.0998x over previous
#include <cuda_runtime.h>
#include <cstdint>

#define N_NODES 50000
#define N_EDGES 600000
#define DIM 128
#define LN_EPS 1e-5f
#define CAP 96            // bucket capacity; dst ~ Poisson(12), P(>=96) ~ 1e-40

// ---- scratch (no allocations allowed) ----
__device__ uint32_t g_agg[(size_t)N_NODES * DIM];   // tf32 bits of agg*in_norm
__device__ int      g_deg_src[N_NODES];
__device__ int      g_fill[N_NODES];                // == in-degree after fill
__device__ int      g_bucket[(size_t)N_NODES * CAP];
__device__ float    g_onorm[N_NODES];
__device__ uint32_t g_wt[2 * DIM * DIM];            // W=[fc_w;res_w] as tf32 bits

static __device__ __forceinline__ uint32_t f2tf32(float f) {
    uint32_t u;
    asm("cvt.rna.tf32.f32 %0, %1;" : "=r"(u) : "f"(f));
    return u;
}

// ---------------------------------------------------------------------------
// 1) zero counters
// ---------------------------------------------------------------------------
__global__ void zero_kernel() {
    int idx = blockIdx.x * blockDim.x + threadIdx.x;
    if (idx < N_NODES) { g_deg_src[idx] = 0; g_fill[idx] = 0; }
}

// ---------------------------------------------------------------------------
// 2) one edge pass: src-degree histogram + dst-binning (fill == in-degree)
// ---------------------------------------------------------------------------
__global__ void fill_kernel(const int* __restrict__ src, const int* __restrict__ dst) {
    int e = blockIdx.x * blockDim.x + threadIdx.x;
    if (e >= N_EDGES) return;
    int d = __ldg(&dst[e]);
    int s = __ldg(&src[e]);
    int pos = atomicAdd(&g_fill[d], 1);
    if (pos < CAP) g_bucket[(size_t)d * CAP + pos] = s;
    atomicAdd(&g_deg_src[s], 1);
}

// ---------------------------------------------------------------------------
// 3) per-src out-norm
// ---------------------------------------------------------------------------
__global__ void onorm_kernel() {
    int i = blockIdx.x * blockDim.x + threadIdx.x;
    if (i < N_NODES) g_onorm[i] = rsqrtf(fmaxf((float)g_deg_src[i], 1.0f));
}

// ---------------------------------------------------------------------------
// 4) pre-convert W rows to tf32 bits (rna)
// ---------------------------------------------------------------------------
__global__ void wconv_kernel(const float* __restrict__ fc_w,
                             const float* __restrict__ res_w) {
    int u = blockIdx.x * blockDim.x + threadIdx.x;   // float4 units: 2*128*128/4
    if (u >= 2 * DIM * DIM / 4) return;
    int kg = u >> 5;
    int n4 = u & 31;
    const float* wrow = (kg < DIM) ? (fc_w + (size_t)kg * DIM)
                                   : (res_w + (size_t)(kg - DIM) * DIM);
    float4 w4 = __ldg((const float4*)wrow + n4);
    uint4 t;
    t.x = f2tf32(w4.x); t.y = f2tf32(w4.y);
    t.z = f2tf32(w4.z); t.w = f2tf32(w4.w);
    *(uint4*)(g_wt + (size_t)kg * DIM + n4 * 4) = t;
}

// ---------------------------------------------------------------------------
// 5) pull-mode gather: one warp per dst node
//    g_agg[d] = tf32( in_norm(d) * sum_{s in bucket[d]} feat[s]*onorm[s] )
// ---------------------------------------------------------------------------
__global__ void gather_kernel(const float* __restrict__ feat) {
    int gid  = blockIdx.x * blockDim.x + threadIdx.x;
    int d    = gid >> 5;
    int lane = gid & 31;
    if (d >= N_NODES) return;

    int fillv = __ldg(&g_fill[d]);
    int cnt   = min(fillv, CAP);
    float4 acc = make_float4(0.f, 0.f, 0.f, 0.f);

    for (int base = 0; base < cnt; base += 32) {
        int nb = min(32, cnt - base);
        int   s  = 0;
        float sc = 0.f;
        if (lane < nb) {
            s  = g_bucket[(size_t)d * CAP + base + lane];
            sc = __ldg(&g_onorm[s]);
        }
#pragma unroll 4
        for (int i = 0; i < nb; i++) {
            int   si  = __shfl_sync(0xffffffffu, s,  i);
            float sci = __shfl_sync(0xffffffffu, sc, i);
            float4 v = __ldg((const float4*)(feat + (size_t)si * DIM) + lane);
            acc.x += sci * v.x; acc.y += sci * v.y;
            acc.z += sci * v.z; acc.w += sci * v.w;
        }
    }
    float inn = rsqrtf(fmaxf((float)fillv, 1.0f));
    uint4 t;
    t.x = f2tf32(acc.x * inn); t.y = f2tf32(acc.y * inn);
    t.z = f2tf32(acc.z * inn); t.w = f2tf32(acc.w * inn);
    ((uint4*)(g_agg + (size_t)d * DIM))[lane] = t;
}

// ---------------------------------------------------------------------------
// 6) mma.sync TF32 GEMM, cp.async double-buffered + bias/residual/LN/ReLU
// ---------------------------------------------------------------------------
#define SA_S 36
#define SB_S 136
#define ABUF (128 * SA_S)          // u32 per A buffer
#define BBUF (32 * SB_S)           // u32 per B buffer
#define DYN_SMEM ((2 * ABUF + 2 * BBUF) * 4)

static __device__ __forceinline__ void cp16(uint32_t saddr, const void* g) {
    asm volatile("cp.async.ca.shared.global [%0], [%1], 16;"
                 :: "r"(saddr), "l"(g) : "memory");
}

static __device__ __forceinline__ void mma_tf32(
    float c[4], const uint32_t a[4], uint32_t b0, uint32_t b1) {
    asm volatile(
        "mma.sync.aligned.m16n8k8.row.col.f32.tf32.tf32.f32 "
        "{%0,%1,%2,%3}, {%4,%5,%6,%7}, {%8,%9}, {%0,%1,%2,%3};"
        : "+f"(c[0]), "+f"(c[1]), "+f"(c[2]), "+f"(c[3])
        : "r"(a[0]), "r"(a[1]), "r"(a[2]), "r"(a[3]), "r"(b0), "r"(b1));
}

__global__ __launch_bounds__(256, 2) void gemm_mma_kernel(
    const float* __restrict__ feat,
    const float* __restrict__ fc_b,
    const float* __restrict__ ln_g,
    const float* __restrict__ ln_b,
    float* __restrict__ out)
{
    extern __shared__ __align__(16) uint32_t dynsm[];
    uint32_t* sA = dynsm;                 // 2 buffers
    uint32_t* sB = dynsm + 2 * ABUF;      // 2 buffers
    __shared__ float sInorm[128], sBias[128], sGam[128], sBet[128];
    __shared__ float sSum[2][128], sSq[2][128];

    const int tid   = threadIdx.x;
    const int lane  = tid & 31;
    const int wid   = tid >> 5;
    const int warpM = wid & 3;
    const int warpN = wid >> 2;
    const int gid   = lane >> 2;
    const int tig   = lane & 3;
    const int bm    = blockIdx.x * 128;

    if (tid < 128) {
        int node = bm + tid;
        float dn = (node < N_NODES) ? (float)g_fill[node] : 1.0f;
        sInorm[tid] = rsqrtf(fmaxf(dn, 1.0f));
        sBias[tid]  = __ldg(&fc_b[tid]);
        sGam[tid]   = __ldg(&ln_g[tid]);
        sBet[tid]   = __ldg(&ln_b[tid]);
    }

    // staging: pure 16B async copies (A: agg-tf32 rows then feat rows; B: g_wt)
    auto stage = [&](int c) {
        uint32_t* dA = sA + (c & 1) * ABUF;
        uint32_t* dB = sB + (c & 1) * BBUF;
#pragma unroll
        for (int i = 0; i < 4; i++) {
            int u = tid + i * 256;
            int m = u >> 3;
            int q = u & 7;
            int node  = bm + m;
            int nodec = (node < N_NODES) ? node : (N_NODES - 1);
            const void* gp;
            if (c < 4)
                gp = g_agg + (size_t)nodec * DIM + c * 32 + q * 4;
            else
                gp = feat + (size_t)nodec * DIM + (c - 4) * 32 + q * 4;
            cp16((uint32_t)__cvta_generic_to_shared(dA + m * SA_S + q * 4), gp);
        }
#pragma unroll
        for (int i = 0; i < 4; i++) {
            int u  = tid + i * 256;
            int kk = u >> 5;
            int n4 = u & 31;
            const void* gp = g_wt + (size_t)(c * 32 + kk) * DIM + n4 * 4;
            cp16((uint32_t)__cvta_generic_to_shared(dB + kk * SB_S + n4 * 4), gp);
        }
        asm volatile("cp.async.commit_group;" ::: "memory");
    };

    float acc[2][8][4];
#pragma unroll
    for (int mt = 0; mt < 2; mt++)
#pragma unroll
        for (int nt = 0; nt < 8; nt++)
#pragma unroll
            for (int e = 0; e < 4; e++) acc[mt][nt][e] = 0.f;

    stage(0);
    for (int c = 0; c < 8; c++) {
        if (c < 7) stage(c + 1);
        if (c < 7) asm volatile("cp.async.wait_group 1;" ::: "memory");
        else       asm volatile("cp.async.wait_group 0;" ::: "memory");
        __syncthreads();

        const uint32_t* cA = sA + (c & 1) * ABUF;
        const uint32_t* cB = sB + (c & 1) * BBUF;
#pragma unroll
        for (int k8 = 0; k8 < 32; k8 += 8) {
            uint32_t af[2][4];
#pragma unroll
            for (int mt = 0; mt < 2; mt++) {
                int row0 = warpM * 32 + mt * 16 + gid;
                af[mt][0] = cA[row0 * SA_S + k8 + tig];
                af[mt][1] = cA[(row0 + 8) * SA_S + k8 + tig];
                af[mt][2] = cA[row0 * SA_S + k8 + tig + 4];
                af[mt][3] = cA[(row0 + 8) * SA_S + k8 + tig + 4];
            }
#pragma unroll
            for (int nt = 0; nt < 8; nt++) {
                int n = warpN * 64 + nt * 8 + gid;
                uint32_t b0 = cB[(k8 + tig) * SB_S + n];
                uint32_t b1 = cB[(k8 + tig + 4) * SB_S + n];
                mma_tf32(acc[0][nt], af[0], b0, b1);
                mma_tf32(acc[1][nt], af[1], b0, b1);
            }
        }
        __syncthreads();   // buffer c&1 free for stage(c+2)
    }

    // ---- epilogue: bias*in_norm, LN partials, LN+ReLU+store ----
#pragma unroll
    for (int mt = 0; mt < 2; mt++) {
#pragma unroll
        for (int h = 0; h < 2; h++) {
            int row = warpM * 32 + mt * 16 + h * 8 + gid;
            float inn = sInorm[row];
            float s = 0.f, q = 0.f;
#pragma unroll
            for (int nt = 0; nt < 8; nt++) {
#pragma unroll
                for (int e = 0; e < 2; e++) {
                    int col = warpN * 64 + nt * 8 + tig * 2 + e;
                    float val = acc[mt][nt][2 * h + e] + inn * sBias[col];
                    acc[mt][nt][2 * h + e] = val;
                    s += val; q += val * val;
                }
            }
            s += __shfl_xor_sync(0xffffffffu, s, 1);
            s += __shfl_xor_sync(0xffffffffu, s, 2);
            q += __shfl_xor_sync(0xffffffffu, q, 1);
            q += __shfl_xor_sync(0xffffffffu, q, 2);
            if (tig == 0) { sSum[warpN][row] = s; sSq[warpN][row] = q; }
        }
    }
    __syncthreads();

#pragma unroll
    for (int mt = 0; mt < 2; mt++) {
#pragma unroll
        for (int h = 0; h < 2; h++) {
            int row = warpM * 32 + mt * 16 + h * 8 + gid;
            int node = bm + row;
            if (node >= N_NODES) continue;
            float s = sSum[0][row] + sSum[1][row];
            float q = sSq[0][row]  + sSq[1][row];
            float mu   = s * (1.0f / DIM);
            float var  = q * (1.0f / DIM) - mu * mu;
            float rstd = rsqrtf(var + LN_EPS);
            float* orow = out + (size_t)node * DIM;
#pragma unroll
            for (int nt = 0; nt < 8; nt++) {
                int col = warpN * 64 + nt * 8 + tig * 2;
                float2 o;
                o.x = fmaxf(0.f, (acc[mt][nt][2*h+0] - mu) * rstd * sGam[col]   + sBet[col]);
                o.y = fmaxf(0.f, (acc[mt][nt][2*h+1] - mu) * rstd * sGam[col+1] + sBet[col+1]);
                *(float2*)(orow + col) = o;
            }
        }
    }
}

// ---------------------------------------------------------------------------
extern "C" void kernel_launch(void* const* d_in, const int* in_sizes, int n_in,
                              void* d_out, int out_size) {
    const float* feat  = (const float*)d_in[0];
    const int*   src   = (const int*)d_in[1];
    const int*   dst   = (const int*)d_in[2];
    const float* fc_w  = (const float*)d_in[3];
    const float* fc_b  = (const float*)d_in[4];
    const float* res_w = (const float*)d_in[5];
    const float* ln_g  = (const float*)d_in[6];
    const float* ln_b  = (const float*)d_in[7];
    float* out = (float*)d_out;

    (void)in_sizes; (void)n_in; (void)out_size;

    cudaFuncSetAttribute(gemm_mma_kernel,
                         cudaFuncAttributeMaxDynamicSharedMemorySize, DYN_SMEM);

    zero_kernel<<<(N_NODES + 255) / 256, 256>>>();
    fill_kernel<<<(N_EDGES + 255) / 256, 256>>>(src, dst);
    onorm_kernel<<<(N_NODES + 255) / 256, 256>>>();
    wconv_kernel<<<(2 * DIM * DIM / 4 + 255) / 256, 256>>>(fc_w, res_w);
    gather_kernel<<<(N_NODES * 32 + 255) / 256, 256>>>(feat);
    gemm_mma_kernel<<<(N_NODES + 127) / 128, 256, DYN_SMEM>>>(feat, fc_b,
                                                              ln_g, ln_b, out);
}

// round 16
// speedup vs baseline: 2.1975x; 1.0255x over previous
#include <cuda_runtime.h>
#include <cstdint>

#define N_NODES 50000
#define N_EDGES 600000
#define DIM 128
#define LN_EPS 1e-5f
#define CAP 96            // bucket capacity; dst ~ Poisson(12), P(>=96) ~ 1e-40

// ---- scratch (no allocations allowed) ----
__device__ uint32_t g_agg[(size_t)N_NODES * DIM];   // tf32 bits of agg*in_norm
__device__ int      g_deg_src[N_NODES];
__device__ int      g_fill[N_NODES];                // == in-degree after fill
__device__ int      g_bucket[(size_t)N_NODES * CAP];
__device__ float    g_onorm[N_NODES];
__device__ uint32_t g_wt[2 * DIM * DIM];            // W=[fc_w;res_w] as tf32 bits

static __device__ __forceinline__ uint32_t f2tf32(float f) {
    uint32_t u;
    asm("cvt.rna.tf32.f32 %0, %1;" : "=r"(u) : "f"(f));
    return u;
}

// ---------------------------------------------------------------------------
// 1) zero counters
// ---------------------------------------------------------------------------
__global__ void zero_kernel() {
    int idx = blockIdx.x * blockDim.x + threadIdx.x;
    if (idx < N_NODES) { g_deg_src[idx] = 0; g_fill[idx] = 0; }
}

// ---------------------------------------------------------------------------
// 2) one edge pass, 4 edges/thread: src-degree histogram + dst-binning
// ---------------------------------------------------------------------------
__global__ void fill_kernel(const int* __restrict__ src, const int* __restrict__ dst) {
    int t = blockIdx.x * blockDim.x + threadIdx.x;   // 150000 int4 units
    if (t >= N_EDGES / 4) return;
    int4 s4 = __ldg((const int4*)src + t);
    int4 d4 = __ldg((const int4*)dst + t);
    int ss[4] = {s4.x, s4.y, s4.z, s4.w};
    int dd[4] = {d4.x, d4.y, d4.z, d4.w};
#pragma unroll
    for (int i = 0; i < 4; i++) {
        int pos = atomicAdd(&g_fill[dd[i]], 1);
        if (pos < CAP) g_bucket[(size_t)dd[i] * CAP + pos] = ss[i];
        atomicAdd(&g_deg_src[ss[i]], 1);
    }
}

// ---------------------------------------------------------------------------
// 3) prep: out-norms (blocks [0,196)) + W tf32 conversion (blocks [196,228))
// ---------------------------------------------------------------------------
#define ONORM_BLKS ((N_NODES + 255) / 256)           // 196
#define WCONV_BLKS ((2 * DIM * DIM / 4 + 255) / 256) // 32

__global__ void prep_kernel(const float* __restrict__ fc_w,
                            const float* __restrict__ res_w) {
    if (blockIdx.x < ONORM_BLKS) {
        int i = blockIdx.x * blockDim.x + threadIdx.x;
        if (i < N_NODES) g_onorm[i] = rsqrtf(fmaxf((float)g_deg_src[i], 1.0f));
    } else {
        int u = (blockIdx.x - ONORM_BLKS) * blockDim.x + threadIdx.x;
        if (u >= 2 * DIM * DIM / 4) return;
        int kg = u >> 5;
        int n4 = u & 31;
        const float* wrow = (kg < DIM) ? (fc_w + (size_t)kg * DIM)
                                       : (res_w + (size_t)(kg - DIM) * DIM);
        float4 w4 = __ldg((const float4*)wrow + n4);
        uint4 t;
        t.x = f2tf32(w4.x); t.y = f2tf32(w4.y);
        t.z = f2tf32(w4.z); t.w = f2tf32(w4.w);
        *(uint4*)(g_wt + (size_t)kg * DIM + n4 * 4) = t;
    }
}

// ---------------------------------------------------------------------------
// 4) pull-mode gather: one warp per dst node
//    g_agg[d] = tf32( in_norm(d) * sum_{s in bucket[d]} feat[s]*onorm[s] )
// ---------------------------------------------------------------------------
__global__ void gather_kernel(const float* __restrict__ feat) {
    int gid  = blockIdx.x * blockDim.x + threadIdx.x;
    int d    = gid >> 5;
    int lane = gid & 31;
    if (d >= N_NODES) return;

    int fillv = __ldg(&g_fill[d]);
    int cnt   = min(fillv, CAP);
    float4 acc = make_float4(0.f, 0.f, 0.f, 0.f);

    for (int base = 0; base < cnt; base += 32) {
        int nb = min(32, cnt - base);
        int   s  = 0;
        float sc = 0.f;
        if (lane < nb) {
            s  = g_bucket[(size_t)d * CAP + base + lane];
            sc = __ldg(&g_onorm[s]);
        }
#pragma unroll 4
        for (int i = 0; i < nb; i++) {
            int   si  = __shfl_sync(0xffffffffu, s,  i);
            float sci = __shfl_sync(0xffffffffu, sc, i);
            float4 v = __ldg((const float4*)(feat + (size_t)si * DIM) + lane);
            acc.x += sci * v.x; acc.y += sci * v.y;
            acc.z += sci * v.z; acc.w += sci * v.w;
        }
    }
    float inn = rsqrtf(fmaxf((float)fillv, 1.0f));
    uint4 t;
    t.x = f2tf32(acc.x * inn); t.y = f2tf32(acc.y * inn);
    t.z = f2tf32(acc.z * inn); t.w = f2tf32(acc.w * inn);
    ((uint4*)(g_agg + (size_t)d * DIM))[lane] = t;
}

// ---------------------------------------------------------------------------
// 5) mma.sync TF32 GEMM, cp.async double-buffered + bias/residual/LN/ReLU
// ---------------------------------------------------------------------------
#define SA_S 36
#define SB_S 136
#define ABUF (128 * SA_S)          // u32 per A buffer
#define BBUF (32 * SB_S)           // u32 per B buffer
#define DYN_SMEM ((2 * ABUF + 2 * BBUF) * 4)

static __device__ __forceinline__ void cp16(uint32_t saddr, const void* g) {
    asm volatile("cp.async.ca.shared.global [%0], [%1], 16;"
                 :: "r"(saddr), "l"(g) : "memory");
}

static __device__ __forceinline__ void mma_tf32(
    float c[4], const uint32_t a[4], uint32_t b0, uint32_t b1) {
    asm volatile(
        "mma.sync.aligned.m16n8k8.row.col.f32.tf32.tf32.f32 "
        "{%0,%1,%2,%3}, {%4,%5,%6,%7}, {%8,%9}, {%0,%1,%2,%3};"
        : "+f"(c[0]), "+f"(c[1]), "+f"(c[2]), "+f"(c[3])
        : "r"(a[0]), "r"(a[1]), "r"(a[2]), "r"(a[3]), "r"(b0), "r"(b1));
}

__global__ __launch_bounds__(256, 2) void gemm_mma_kernel(
    const float* __restrict__ feat,
    const float* __restrict__ fc_b,
    const float* __restrict__ ln_g,
    const float* __restrict__ ln_b,
    float* __restrict__ out)
{
    extern __shared__ __align__(16) uint32_t dynsm[];
    uint32_t* sA = dynsm;                 // 2 buffers
    uint32_t* sB = dynsm + 2 * ABUF;      // 2 buffers
    __shared__ float sInorm[128], sBias[128], sGam[128], sBet[128];
    __shared__ float sSum[2][128], sSq[2][128];

    const int tid   = threadIdx.x;
    const int lane  = tid & 31;
    const int wid   = tid >> 5;
    const int warpM = wid & 3;
    const int warpN = wid >> 2;
    const int gid   = lane >> 2;
    const int tig   = lane & 3;
    const int bm    = blockIdx.x * 128;

    if (tid < 128) {
        int node = bm + tid;
        float dn = (node < N_NODES) ? (float)g_fill[node] : 1.0f;
        sInorm[tid] = rsqrtf(fmaxf(dn, 1.0f));
        sBias[tid]  = __ldg(&fc_b[tid]);
        sGam[tid]   = __ldg(&ln_g[tid]);
        sBet[tid]   = __ldg(&ln_b[tid]);
    }

    auto stage = [&](int c) {
        uint32_t* dA = sA + (c & 1) * ABUF;
        uint32_t* dB = sB + (c & 1) * BBUF;
#pragma unroll
        for (int i = 0; i < 4; i++) {
            int u = tid + i * 256;
            int m = u >> 3;
            int q = u & 7;
            int node  = bm + m;
            int nodec = (node < N_NODES) ? node : (N_NODES - 1);
            const void* gp;
            if (c < 4)
                gp = g_agg + (size_t)nodec * DIM + c * 32 + q * 4;
            else
                gp = feat + (size_t)nodec * DIM + (c - 4) * 32 + q * 4;
            cp16((uint32_t)__cvta_generic_to_shared(dA + m * SA_S + q * 4), gp);
        }
#pragma unroll
        for (int i = 0; i < 4; i++) {
            int u  = tid + i * 256;
            int kk = u >> 5;
            int n4 = u & 31;
            const void* gp = g_wt + (size_t)(c * 32 + kk) * DIM + n4 * 4;
            cp16((uint32_t)__cvta_generic_to_shared(dB + kk * SB_S + n4 * 4), gp);
        }
        asm volatile("cp.async.commit_group;" ::: "memory");
    };

    float acc[2][8][4];
#pragma unroll
    for (int mt = 0; mt < 2; mt++)
#pragma unroll
        for (int nt = 0; nt < 8; nt++)
#pragma unroll
            for (int e = 0; e < 4; e++) acc[mt][nt][e] = 0.f;

    stage(0);
    for (int c = 0; c < 8; c++) {
        if (c < 7) stage(c + 1);
        if (c < 7) asm volatile("cp.async.wait_group 1;" ::: "memory");
        else       asm volatile("cp.async.wait_group 0;" ::: "memory");
        __syncthreads();

        const uint32_t* cA = sA + (c & 1) * ABUF;
        const uint32_t* cB = sB + (c & 1) * BBUF;
#pragma unroll
        for (int k8 = 0; k8 < 32; k8 += 8) {
            uint32_t af[2][4];
#pragma unroll
            for (int mt = 0; mt < 2; mt++) {
                int row0 = warpM * 32 + mt * 16 + gid;
                af[mt][0] = cA[row0 * SA_S + k8 + tig];
                af[mt][1] = cA[(row0 + 8) * SA_S + k8 + tig];
                af[mt][2] = cA[row0 * SA_S + k8 + tig + 4];
                af[mt][3] = cA[(row0 + 8) * SA_S + k8 + tig + 4];
            }
#pragma unroll
            for (int nt = 0; nt < 8; nt++) {
                int n = warpN * 64 + nt * 8 + gid;
                uint32_t b0 = cB[(k8 + tig) * SB_S + n];
                uint32_t b1 = cB[(k8 + tig + 4) * SB_S + n];
                mma_tf32(acc[0][nt], af[0], b0, b1);
                mma_tf32(acc[1][nt], af[1], b0, b1);
            }
        }
        __syncthreads();   // buffer c&1 free for stage(c+2)
    }

    // ---- epilogue: bias*in_norm, LN partials, LN+ReLU+store ----
#pragma unroll
    for (int mt = 0; mt < 2; mt++) {
#pragma unroll
        for (int h = 0; h < 2; h++) {
            int row = warpM * 32 + mt * 16 + h * 8 + gid;
            float inn = sInorm[row];
            float s = 0.f, q = 0.f;
#pragma unroll
            for (int nt = 0; nt < 8; nt++) {
#pragma unroll
                for (int e = 0; e < 2; e++) {
                    int col = warpN * 64 + nt * 8 + tig * 2 + e;
                    float val = acc[mt][nt][2 * h + e] + inn * sBias[col];
                    acc[mt][nt][2 * h + e] = val;
                    s += val; q += val * val;
                }
            }
            s += __shfl_xor_sync(0xffffffffu, s, 1);
            s += __shfl_xor_sync(0xffffffffu, s, 2);
            q += __shfl_xor_sync(0xffffffffu, q, 1);
            q += __shfl_xor_sync(0xffffffffu, q, 2);
            if (tig == 0) { sSum[warpN][row] = s; sSq[warpN][row] = q; }
        }
    }
    __syncthreads();

#pragma unroll
    for (int mt = 0; mt < 2; mt++) {
#pragma unroll
        for (int h = 0; h < 2; h++) {
            int row = warpM * 32 + mt * 16 + h * 8 + gid;
            int node = bm + row;
            if (node >= N_NODES) continue;
            float s = sSum[0][row] + sSum[1][row];
            float q = sSq[0][row]  + sSq[1][row];
            float mu   = s * (1.0f / DIM);
            float var  = q * (1.0f / DIM) - mu * mu;
            float rstd = rsqrtf(var + LN_EPS);
            float* orow = out + (size_t)node * DIM;
#pragma unroll
            for (int nt = 0; nt < 8; nt++) {
                int col = warpN * 64 + nt * 8 + tig * 2;
                float2 o;
                o.x = fmaxf(0.f, (acc[mt][nt][2*h+0] - mu) * rstd * sGam[col]   + sBet[col]);
                o.y = fmaxf(0.f, (acc[mt][nt][2*h+1] - mu) * rstd * sGam[col+1] + sBet[col+1]);
                *(float2*)(orow + col) = o;
            }
        }
    }
}

// ---------------------------------------------------------------------------
extern "C" void kernel_launch(void* const* d_in, const int* in_sizes, int n_in,
                              void* d_out, int out_size) {
    const float* feat  = (const float*)d_in[0];
    const int*   src   = (const int*)d_in[1];
    const int*   dst   = (const int*)d_in[2];
    const float* fc_w  = (const float*)d_in[3];
    const float* fc_b  = (const float*)d_in[4];
    const float* res_w = (const float*)d_in[5];
    const float* ln_g  = (const float*)d_in[6];
    const float* ln_b  = (const float*)d_in[7];
    float* out = (float*)d_out;

    (void)in_sizes; (void)n_in; (void)out_size;

    cudaFuncSetAttribute(gemm_mma_kernel,
                         cudaFuncAttributeMaxDynamicSharedMemorySize, DYN_SMEM);

    zero_kernel<<<(N_NODES + 255) / 256, 256>>>();
    fill_kernel<<<(N_EDGES / 4 + 255) / 256, 256>>>(src, dst);
    prep_kernel<<<ONORM_BLKS + WCONV_BLKS, 256>>>(fc_w, res_w);
    gather_kernel<<<(N_NODES * 32 + 255) / 256, 256>>>(feat);
    gemm_mma_kernel<<<(N_NODES + 127) / 128, 256, DYN_SMEM>>>(feat, fc_b,
                                                              ln_g, ln_b, out);
}